// round 16
// baseline (speedup 1.0000x reference)
#include <cuda_runtime.h>
#include <cuda_bf16.h>

typedef unsigned int u32;

#define BATCH 32
#define SEQ   768
#define CDIM  256
#define HDIM  64
#define ROWS  (BATCH * SEQ)   // 24576

// split-bf16 scratch: one row = 64 bf16 = 8 uint4
__device__ uint4 g_qhi[ROWS * 8];
__device__ uint4 g_khi[ROWS * 8];
__device__ uint4 g_vhi[ROWS * 8];
__device__ uint4 g_vlo[ROWS * 8];
// pre-split x: [ROWS][256] bf16 = 32 uint4 per row
__device__ uint4 g_xhi[ROWS * 32];
__device__ uint4 g_xlo[ROWS * 32];
// pre-split w: 3 x [256][64] bf16 = 2048 uint4 each
__device__ uint4 g_whi[3 * 2048];
__device__ uint4 g_wlo[3 * 2048];

// ---------------------------------------------------------------- helpers
__device__ __forceinline__ u32 smem_u32(const void* p) {
    u32 a; asm("{ .reg .u64 t; cvta.to.shared.u64 t, %1; cvt.u32.u64 %0, t; }" : "=r"(a) : "l"(p));
    return a;
}
__device__ __forceinline__ u32 swz_addr(u32 base, int row, int chunk) {
    return base + (row << 7) + (((chunk ^ (row & 7))) << 4);
}
__device__ __forceinline__ u32 addr_A(u32 base, int lane, int m0, int k0) {
    int row = m0 + (lane & 15);
    int ch  = (k0 >> 3) + (lane >> 4);
    return swz_addr(base, row, ch);
}
__device__ __forceinline__ u32 addr_B(u32 base, int lane, int n0, int k0) {
    int row = n0 + (lane & 7) + ((lane >> 4) << 3);
    int ch  = (k0 >> 3) + ((lane >> 3) & 1);
    return swz_addr(base, row, ch);
}
__device__ __forceinline__ void ldm4(u32* r, u32 a) {
    asm volatile("ldmatrix.sync.aligned.m8n8.x4.shared.b16 {%0,%1,%2,%3}, [%4];"
                 : "=r"(r[0]), "=r"(r[1]), "=r"(r[2]), "=r"(r[3]) : "r"(a));
}
__device__ __forceinline__ void ldm4t(u32* r, u32 a) {
    asm volatile("ldmatrix.sync.aligned.m8n8.x4.trans.shared.b16 {%0,%1,%2,%3}, [%4];"
                 : "=r"(r[0]), "=r"(r[1]), "=r"(r[2]), "=r"(r[3]) : "r"(a));
}
__device__ __forceinline__ void mma_bf(float* c, const u32* a, const u32* b) {
    asm volatile("mma.sync.aligned.m16n8k16.row.col.f32.bf16.bf16.f32 "
                 "{%0,%1,%2,%3},{%4,%5,%6,%7},{%8,%9},{%0,%1,%2,%3};"
                 : "+f"(c[0]), "+f"(c[1]), "+f"(c[2]), "+f"(c[3])
                 : "r"(a[0]), "r"(a[1]), "r"(a[2]), "r"(a[3]), "r"(b[0]), "r"(b[1]));
}
__device__ __forceinline__ void cp16(u32 d, const void* s) {
    asm volatile("cp.async.cg.shared.global [%0], [%1], 16;" :: "r"(d), "l"(s));
}
#define CP_COMMIT() asm volatile("cp.async.commit_group;" ::: "memory")
#define CP_WAIT0()  asm volatile("cp.async.wait_group 0;" ::: "memory")

__device__ __forceinline__ u32 pk(float a, float b) {
    __nv_bfloat162 r = __floats2bfloat162_rn(a, b);
    return *reinterpret_cast<u32*>(&r);
}
__device__ __forceinline__ float bf_hi(float f) {
    return __bfloat162float(__float2bfloat16_rn(f));
}
__device__ __forceinline__ float ex2(float x) {
    float r; asm("ex2.approx.f32 %0, %1;" : "=f"(r) : "f"(x)); return r;
}

// ---------------------------------------------------------------- kernel 0
__global__ __launch_bounds__(256) void split_kernel(
    const float* __restrict__ x, const float* __restrict__ wq,
    const float* __restrict__ wk, const float* __restrict__ wv)
{
    const int t = threadIdx.x, bx = blockIdx.x;
    if (bx < 384) {
        float4 a[8], b[8];
        int e[8];
        #pragma unroll
        for (int i = 0; i < 8; i++) {
            e[i] = bx * 256 + t + i * 98304;
            const float* s = x + (size_t)e[i] * 8;
            a[i] = *(const float4*)s;
            b[i] = *(const float4*)(s + 4);
        }
        #pragma unroll
        for (int i = 0; i < 8; i++) {
            float f[8] = {a[i].x, a[i].y, a[i].z, a[i].w, b[i].x, b[i].y, b[i].z, b[i].w};
            u32 hi[4], lo[4];
            #pragma unroll
            for (int u = 0; u < 4; u++) {
                float h0 = bf_hi(f[2 * u]), h1 = bf_hi(f[2 * u + 1]);
                hi[u] = pk(h0, h1);
                lo[u] = pk(f[2 * u] - h0, f[2 * u + 1] - h1);
            }
            g_xhi[e[i]] = make_uint4(hi[0], hi[1], hi[2], hi[3]);
            g_xlo[e[i]] = make_uint4(lo[0], lo[1], lo[2], lo[3]);
        }
    } else {
        float4 a[4], b[4];
        int e[4];
        #pragma unroll
        for (int i = 0; i < 4; i++) {
            e[i] = (bx - 384) * 256 + t + i * 1536;
            int which = e[i] >> 11;
            int wo = (e[i] & 2047) * 8;
            const float* s = ((which == 0) ? wq : (which == 1) ? wk : wv) + wo;
            a[i] = *(const float4*)s;
            b[i] = *(const float4*)(s + 4);
        }
        #pragma unroll
        for (int i = 0; i < 4; i++) {
            float f[8] = {a[i].x, a[i].y, a[i].z, a[i].w, b[i].x, b[i].y, b[i].z, b[i].w};
            u32 hi[4], lo[4];
            #pragma unroll
            for (int u = 0; u < 4; u++) {
                float h0 = bf_hi(f[2 * u]), h1 = bf_hi(f[2 * u + 1]);
                hi[u] = pk(h0, h1);
                lo[u] = pk(f[2 * u] - h0, f[2 * u + 1] - h1);
            }
            g_whi[e[i]] = make_uint4(hi[0], hi[1], hi[2], hi[3]);
            g_wlo[e[i]] = make_uint4(lo[0], lo[1], lo[2], lo[3]);
        }
    }
}

// ---------------------------------------------------------------- kernel 1
// QKV: 256 threads, 8 warps = 4m(32 rows) x 2n(32 cols). 32x32 warp tiles.
#define QS_XHI 0
#define QS_XLO 16384
#define QS_WHI 32768
#define QS_WLO 40960
#define QS_SIZE 49152
#define QKV_SMEM (2 * QS_SIZE)     // 98304

__global__ __launch_bounds__(256, 2) void qkv_kernel()
{
    extern __shared__ char smc[];
    const u32 sb = smem_u32(smc);
    const int t = threadIdx.x, lane = t & 31, wid = t >> 5;
    const int wm = wid & 3, wn = wid >> 2;       // 4m x 2n
    const int m0 = wm * 32;
    const int r0 = blockIdx.x * 128;
    const int which = blockIdx.y;

    {
        const u32 stg = sb;
        #pragma unroll
        for (int rep = 0; rep < 4; rep++) {
            int idx = t + rep * 256, r = idx >> 3, c = idx & 7;
            u32 off = (u32)(r << 7) + (u32)((c ^ (r & 7)) << 4);
            cp16(stg + QS_XHI + off, &g_xhi[(size_t)(r0 + r) * 32 + c]);
            cp16(stg + QS_XLO + off, &g_xlo[(size_t)(r0 + r) * 32 + c]);
        }
        #pragma unroll
        for (int rep = 0; rep < 2; rep++) {
            int idx = t + rep * 256, r = idx >> 3, c = idx & 7;
            u32 off = (u32)(r << 7) + (u32)((c ^ (r & 7)) << 4);
            cp16(stg + QS_WHI + off, &g_whi[which * 2048 + r * 8 + c]);
            cp16(stg + QS_WLO + off, &g_wlo[which * 2048 + r * 8 + c]);
        }
        CP_COMMIT();
    }

    float acc[2][4][4];
    #pragma unroll
    for (int i = 0; i < 2; i++)
        #pragma unroll
        for (int j = 0; j < 4; j++)
            #pragma unroll
            for (int k = 0; k < 4; k++) acc[i][j][k] = 0.f;

    for (int ch = 0; ch < 4; ch++) {
        CP_WAIT0();
        __syncthreads();
        if (ch < 3) {
            const u32 stg = sb + (u32)((ch + 1) & 1) * QS_SIZE;
            #pragma unroll
            for (int rep = 0; rep < 4; rep++) {
                int idx = t + rep * 256, r = idx >> 3, c = idx & 7;
                u32 off = (u32)(r << 7) + (u32)((c ^ (r & 7)) << 4);
                cp16(stg + QS_XHI + off, &g_xhi[(size_t)(r0 + r) * 32 + (ch + 1) * 8 + c]);
                cp16(stg + QS_XLO + off, &g_xlo[(size_t)(r0 + r) * 32 + (ch + 1) * 8 + c]);
            }
            #pragma unroll
            for (int rep = 0; rep < 2; rep++) {
                int idx = t + rep * 256, r = idx >> 3, c = idx & 7;
                u32 off = (u32)(r << 7) + (u32)((c ^ (r & 7)) << 4);
                cp16(stg + QS_WHI + off, &g_whi[which * 2048 + ((ch + 1) * 64 + r) * 8 + c]);
                cp16(stg + QS_WLO + off, &g_wlo[which * 2048 + ((ch + 1) * 64 + r) * 8 + c]);
            }
            CP_COMMIT();
        }
        const u32 cur = sb + (u32)(ch & 1) * QS_SIZE;
        #pragma unroll
        for (int k16 = 0; k16 < 4; k16++) {
            int k0 = k16 * 16;
            u32 ah[2][4], al[2][4];
            #pragma unroll
            for (int ms = 0; ms < 2; ms++) {
                ldm4(ah[ms], addr_A(cur + QS_XHI, lane, m0 + ms * 16, k0));
                ldm4(al[ms], addr_A(cur + QS_XLO, lane, m0 + ms * 16, k0));
            }
            #pragma unroll
            for (int np = 0; np < 2; np++) {
                u32 bh[4], bl[4];
                ldm4t(bh, addr_A(cur + QS_WHI, lane, k0, wn * 32 + np * 16));
                ldm4t(bl, addr_A(cur + QS_WLO, lane, k0, wn * 32 + np * 16));
                #pragma unroll
                for (int ms = 0; ms < 2; ms++) {
                    mma_bf(acc[ms][np * 2],     ah[ms], bh);
                    mma_bf(acc[ms][np * 2 + 1], ah[ms], bh + 2);
                    mma_bf(acc[ms][np * 2],     ah[ms], bl);
                    mma_bf(acc[ms][np * 2 + 1], ah[ms], bl + 2);
                    mma_bf(acc[ms][np * 2],     al[ms], bh);
                    mma_bf(acc[ms][np * 2 + 1], al[ms], bh + 2);
                }
            }
        }
    }

    const float scale = (which == 0) ? 0.18033688f : 1.0f;
    u32* dh = (u32*)((which == 0) ? g_qhi : (which == 1) ? g_khi : g_vhi);
    u32* dl = (u32*)g_vlo;                       // only V keeps a lo part
    const bool write_lo = (which == 2);
    const int g = lane >> 2, tt = (lane & 3) * 2;
    #pragma unroll
    for (int ms = 0; ms < 2; ms++)
        #pragma unroll
        for (int nf = 0; nf < 4; nf++)
            #pragma unroll
            for (int gg = 0; gg < 2; gg++) {
                int row = r0 + m0 + ms * 16 + g + gg * 8;
                int col = wn * 32 + nf * 8 + tt;
                float v0 = acc[ms][nf][gg * 2] * scale;
                float v1 = acc[ms][nf][gg * 2 + 1] * scale;
                float h0 = bf_hi(v0), h1 = bf_hi(v1);
                dh[row * 32 + (col >> 1)] = pk(h0, h1);
                if (write_lo)
                    dl[row * 32 + (col >> 1)] = pk(v0 - h0, v1 - h1);
            }
}

// ---------------------------------------------------------------- kernel 2
// Flash attention, balanced pairing. Grid 384 = 32 batches x 12 pairs.
// CTA handles 32-row subtiles j and 23-j (13 key-tile units each CTA).
// 128 threads = 2m(16 rows) x 2kg(32 keys). Q_lo and K_lo dropped in S
// (predicted err ~7e-4 < 1e-3); V fully split in PV (3-term, verified).
// Stage = KH+VH+VL = 24KB; smem 52KB -> 4 CTAs/SM.
#define AQH 0
#define AKV 4096
#define ASTG 24576         // per stage: KH +0, VH +8K, VL +16K
#define A_SMEM (AKV + 2 * ASTG)  // 53248
#define RSTRIDE 72

__global__ __launch_bounds__(128, 4) void attn_kernel(float* __restrict__ out)
{
    extern __shared__ char smc[];
    const u32 sb = smem_u32(smc);
    const int t = threadIdx.x, lane = t & 31, wid = t >> 5;
    const int wm = wid & 1, wg = wid >> 1;       // 2 row-warps x 2 key-groups
    const int m0 = wm * 16;
    const int b  = blockIdx.x & 31;
    const int pr = (int)(blockIdx.x >> 5);       // pair id 0..11
    const size_t tok0 = (size_t)b * SEQ;
    const int g = lane >> 2, tt = (lane & 3) * 2;

    for (int phase = 0; phase < 2; phase++) {
        const int j   = phase ? (23 - pr) : pr;  // subtile 0..23
        const int q0  = j * 32;
        const int nkt = (j >> 1) + 1;            // key tiles (64 keys each)

        __syncthreads();                          // prev phase epilogue done

        // prologue: Q hi (32 rows) + KV tile 0
        #pragma unroll
        for (int rep = 0; rep < 2; rep++) {
            int idx = t + rep * 128, r = idx >> 3, c = idx & 7;
            u32 off = (u32)(r << 7) + (u32)((c ^ (r & 7)) << 4);
            cp16(sb + AQH + off, &g_qhi[(tok0 + q0 + r) * 8 + c]);
        }
        #pragma unroll
        for (int rep = 0; rep < 4; rep++) {
            int idx = t + rep * 128, r = idx >> 3, c = idx & 7;
            u32 off = (u32)(r << 7) + (u32)((c ^ (r & 7)) << 4);
            cp16(sb + AKV + 0     + off, &g_khi[(tok0 + r) * 8 + c]);
            cp16(sb + AKV + 8192  + off, &g_vhi[(tok0 + r) * 8 + c]);
            cp16(sb + AKV + 16384 + off, &g_vlo[(tok0 + r) * 8 + c]);
        }
        CP_COMMIT();

        float oacc[8][4];
        #pragma unroll
        for (int i = 0; i < 8; i++)
            #pragma unroll
            for (int jj = 0; jj < 4; jj++) oacc[i][jj] = 0.f;
        float ls0 = 0.f, ls1 = 0.f;

        for (int kt = 0; kt < nkt; kt++) {
            CP_WAIT0();                           // tile kt resident
            __syncthreads();                      // all warps done with other stage
            if (kt + 1 < nkt) {                   // issue next tile
                const u32 stg = sb + AKV + (u32)((kt + 1) & 1) * ASTG;
                const size_t nb = tok0 + (size_t)(kt + 1) * 64;
                #pragma unroll
                for (int rep = 0; rep < 4; rep++) {
                    int idx = t + rep * 128, r = idx >> 3, c = idx & 7;
                    u32 off = (u32)(r << 7) + (u32)((c ^ (r & 7)) << 4);
                    cp16(stg + 0     + off, &g_khi[(nb + r) * 8 + c]);
                    cp16(stg + 8192  + off, &g_vhi[(nb + r) * 8 + c]);
                    cp16(stg + 16384 + off, &g_vlo[(nb + r) * 8 + c]);
                }
                CP_COMMIT();
            }
            const u32 cur = sb + AKV + (u32)(kt & 1) * ASTG;

            const bool last = (kt == nkt - 1);
            const int kb0 = kt * 64 + wg * 32;
            if (!last || kb0 <= q0 + m0 + 15) {   // warp-granular causal skip
                // ---- S = Qhi Khi^T (16 rows x 32 keys), single term
                float sacc[4][4];
                #pragma unroll
                for (int i = 0; i < 4; i++)
                    #pragma unroll
                    for (int jj = 0; jj < 4; jj++) sacc[i][jj] = 0.f;
                #pragma unroll
                for (int k16 = 0; k16 < 4; k16++) {
                    int k0 = k16 * 16;
                    u32 ah[4];
                    ldm4(ah, addr_A(sb + AQH, lane, m0, k0));
                    #pragma unroll
                    for (int np = 0; np < 2; np++) {
                        int n0 = wg * 32 + np * 16;
                        u32 bh[4];
                        ldm4(bh, addr_B(cur + 0, lane, n0, k0));
                        mma_bf(sacc[np * 2],     ah, bh);
                        mma_bf(sacc[np * 2 + 1], ah, bh + 2);
                    }
                }

                // ---- softmax (fixed bias; scale*log2e folded into Q)
                const int rowg = q0 + m0 + g;
                u32 ph[2][4], pl[2][4];
                #pragma unroll
                for (int f = 0; f < 4; f++) {
                    int cb = kb0 + f * 8 + tt;
                    float p0 = ex2(sacc[f][0]), p1 = ex2(sacc[f][1]);
                    float p2 = ex2(sacc[f][2]), p3 = ex2(sacc[f][3]);
                    if (last) {
                        if (cb     > rowg)     p0 = 0.f;
                        if (cb + 1 > rowg)     p1 = 0.f;
                        if (cb     > rowg + 8) p2 = 0.f;
                        if (cb + 1 > rowg + 8) p3 = 0.f;
                    }
                    ls0 += p0 + p1;
                    ls1 += p2 + p3;
                    float h0 = bf_hi(p0), h1 = bf_hi(p1), h2 = bf_hi(p2), h3 = bf_hi(p3);
                    int jf = f >> 1, hv = (f & 1) * 2;
                    ph[jf][hv]     = pk(h0, h1);
                    ph[jf][hv + 1] = pk(h2, h3);
                    pl[jf][hv]     = pk(p0 - h0, p1 - h1);
                    pl[jf][hv + 1] = pk(p2 - h2, p3 - h3);
                }

                // ---- O += P V over this group's 32 keys (3-term split)
                #pragma unroll
                for (int np = 0; np < 4; np++) {
                    int n0 = np * 16;
                    #pragma unroll
                    for (int jj = 0; jj < 2; jj++) {
                        int k0v = wg * 32 + jj * 16;
                        u32 bh[4], bl[4];
                        ldm4t(bh, addr_A(cur + 8192,  lane, k0v, n0));
                        ldm4t(bl, addr_A(cur + 16384, lane, k0v, n0));
                        mma_bf(oacc[np * 2],     ph[jj], bh);
                        mma_bf(oacc[np * 2 + 1], ph[jj], bh + 2);
                        mma_bf(oacc[np * 2],     ph[jj], bl);
                        mma_bf(oacc[np * 2 + 1], ph[jj], bl + 2);
                        mma_bf(oacc[np * 2],     pl[jj], bh);
                        mma_bf(oacc[np * 2 + 1], pl[jj], bh + 2);
                    }
                }
            }
        }

        // ---- cross-group reduction: wg1 -> smem, wg0 adds + writes
        ls0 += __shfl_xor_sync(0xffffffffu, ls0, 1);
        ls0 += __shfl_xor_sync(0xffffffffu, ls0, 2);
        ls1 += __shfl_xor_sync(0xffffffffu, ls1, 1);
        ls1 += __shfl_xor_sync(0xffffffffu, ls1, 2);

        __syncthreads();                          // all PV reads of KV smem done
        float* red  = (float*)(smc + AKV);                    // 32 x RSTRIDE
        float* lred = (float*)(smc + AKV + 32 * RSTRIDE * 4); // 32 floats

        if (wg == 1) {
            int row0 = m0 + g;
            #pragma unroll
            for (int np = 0; np < 4; np++)
                #pragma unroll
                for (int h = 0; h < 2; h++) {
                    int col = np * 16 + h * 8 + tt;
                    *(float2*)&red[row0 * RSTRIDE + col] =
                        make_float2(oacc[np * 2 + h][0], oacc[np * 2 + h][1]);
                    *(float2*)&red[(row0 + 8) * RSTRIDE + col] =
                        make_float2(oacc[np * 2 + h][2], oacc[np * 2 + h][3]);
                }
            if ((lane & 3) == 0) {
                lred[row0]     = ls0;
                lred[row0 + 8] = ls1;
            }
        }
        __syncthreads();
        if (wg == 0) {
            int row0 = m0 + g;
            float inv0 = 1.0f / (ls0 + lred[row0]);
            float inv1 = 1.0f / (ls1 + lred[row0 + 8]);
            float* op0 = out + (tok0 + q0 + row0) * HDIM;
            float* op1 = out + (tok0 + q0 + row0 + 8) * HDIM;
            #pragma unroll
            for (int np = 0; np < 4; np++)
                #pragma unroll
                for (int h = 0; h < 2; h++) {
                    int col = np * 16 + h * 8 + tt;
                    float2 a0 = *(float2*)&red[row0 * RSTRIDE + col];
                    float2 a1 = *(float2*)&red[(row0 + 8) * RSTRIDE + col];
                    *(float2*)(op0 + col) = make_float2(
                        (oacc[np * 2 + h][0] + a0.x) * inv0,
                        (oacc[np * 2 + h][1] + a0.y) * inv0);
                    *(float2*)(op1 + col) = make_float2(
                        (oacc[np * 2 + h][2] + a1.x) * inv1,
                        (oacc[np * 2 + h][3] + a1.y) * inv1);
                }
        }
    }
}

// ---------------------------------------------------------------- launch
extern "C" void kernel_launch(void* const* d_in, const int* in_sizes, int n_in,
                              void* d_out, int out_size)
{
    const float* x  = (const float*)d_in[0];
    const float* wq = (const float*)d_in[1];
    const float* wk = (const float*)d_in[2];
    const float* wv = (const float*)d_in[3];
    float* out = (float*)d_out;

    cudaFuncSetAttribute(qkv_kernel,  cudaFuncAttributeMaxDynamicSharedMemorySize, QKV_SMEM);
    cudaFuncSetAttribute(attn_kernel, cudaFuncAttributeMaxDynamicSharedMemorySize, A_SMEM);

    split_kernel<<<390, 256>>>(x, wq, wk, wv);
    qkv_kernel<<<dim3(192, 3), 256, QKV_SMEM>>>();
    attn_kernel<<<384, 128, A_SMEM>>>(out);
}

// round 17
// speedup vs baseline: 1.5139x; 1.5139x over previous
#include <cuda_runtime.h>
#include <cuda_bf16.h>

typedef unsigned int u32;

#define BATCH 32
#define SEQ   768
#define CDIM  256
#define HDIM  64
#define ROWS  (BATCH * SEQ)   // 24576

// split-bf16 scratch: one row = 64 bf16 = 8 uint4
__device__ uint4 g_qhi[ROWS * 8];
__device__ uint4 g_khi[ROWS * 8];
__device__ uint4 g_vhi[ROWS * 8];
__device__ uint4 g_vlo[ROWS * 8];
// pre-split x: [ROWS][256] bf16 = 32 uint4 per row
__device__ uint4 g_xhi[ROWS * 32];
__device__ uint4 g_xlo[ROWS * 32];
// pre-split w: 3 x [256][64] bf16 = 2048 uint4 each
__device__ uint4 g_whi[3 * 2048];
__device__ uint4 g_wlo[3 * 2048];

// ---------------------------------------------------------------- helpers
__device__ __forceinline__ u32 smem_u32(const void* p) {
    u32 a; asm("{ .reg .u64 t; cvta.to.shared.u64 t, %1; cvt.u32.u64 %0, t; }" : "=r"(a) : "l"(p));
    return a;
}
__device__ __forceinline__ u32 swz_addr(u32 base, int row, int chunk) {
    return base + (row << 7) + (((chunk ^ (row & 7))) << 4);
}
__device__ __forceinline__ u32 addr_A(u32 base, int lane, int m0, int k0) {
    int row = m0 + (lane & 15);
    int ch  = (k0 >> 3) + (lane >> 4);
    return swz_addr(base, row, ch);
}
__device__ __forceinline__ u32 addr_B(u32 base, int lane, int n0, int k0) {
    int row = n0 + (lane & 7) + ((lane >> 4) << 3);
    int ch  = (k0 >> 3) + ((lane >> 3) & 1);
    return swz_addr(base, row, ch);
}
__device__ __forceinline__ void ldm4(u32* r, u32 a) {
    asm volatile("ldmatrix.sync.aligned.m8n8.x4.shared.b16 {%0,%1,%2,%3}, [%4];"
                 : "=r"(r[0]), "=r"(r[1]), "=r"(r[2]), "=r"(r[3]) : "r"(a));
}
__device__ __forceinline__ void ldm4t(u32* r, u32 a) {
    asm volatile("ldmatrix.sync.aligned.m8n8.x4.trans.shared.b16 {%0,%1,%2,%3}, [%4];"
                 : "=r"(r[0]), "=r"(r[1]), "=r"(r[2]), "=r"(r[3]) : "r"(a));
}
__device__ __forceinline__ void mma_bf(float* c, const u32* a, const u32* b) {
    asm volatile("mma.sync.aligned.m16n8k16.row.col.f32.bf16.bf16.f32 "
                 "{%0,%1,%2,%3},{%4,%5,%6,%7},{%8,%9},{%0,%1,%2,%3};"
                 : "+f"(c[0]), "+f"(c[1]), "+f"(c[2]), "+f"(c[3])
                 : "r"(a[0]), "r"(a[1]), "r"(a[2]), "r"(a[3]), "r"(b[0]), "r"(b[1]));
}
__device__ __forceinline__ void cp16(u32 d, const void* s) {
    asm volatile("cp.async.cg.shared.global [%0], [%1], 16;" :: "r"(d), "l"(s));
}
#define CP_COMMIT() asm volatile("cp.async.commit_group;" ::: "memory")
#define CP_WAIT0()  asm volatile("cp.async.wait_group 0;" ::: "memory")

__device__ __forceinline__ u32 pk(float a, float b) {
    __nv_bfloat162 r = __floats2bfloat162_rn(a, b);
    return *reinterpret_cast<u32*>(&r);
}
__device__ __forceinline__ float bf_hi(float f) {
    return __bfloat162float(__float2bfloat16_rn(f));
}
__device__ __forceinline__ float ex2(float x) {
    float r; asm("ex2.approx.f32 %0, %1;" : "=f"(r) : "f"(x)); return r;
}

// ---------------------------------------------------------------- kernel 0
__global__ __launch_bounds__(256) void split_kernel(
    const float* __restrict__ x, const float* __restrict__ wq,
    const float* __restrict__ wk, const float* __restrict__ wv)
{
    const int t = threadIdx.x, bx = blockIdx.x;
    if (bx < 384) {
        float4 a[8], b[8];
        int e[8];
        #pragma unroll
        for (int i = 0; i < 8; i++) {
            e[i] = bx * 256 + t + i * 98304;
            const float* s = x + (size_t)e[i] * 8;
            a[i] = *(const float4*)s;
            b[i] = *(const float4*)(s + 4);
        }
        #pragma unroll
        for (int i = 0; i < 8; i++) {
            float f[8] = {a[i].x, a[i].y, a[i].z, a[i].w, b[i].x, b[i].y, b[i].z, b[i].w};
            u32 hi[4], lo[4];
            #pragma unroll
            for (int u = 0; u < 4; u++) {
                float h0 = bf_hi(f[2 * u]), h1 = bf_hi(f[2 * u + 1]);
                hi[u] = pk(h0, h1);
                lo[u] = pk(f[2 * u] - h0, f[2 * u + 1] - h1);
            }
            g_xhi[e[i]] = make_uint4(hi[0], hi[1], hi[2], hi[3]);
            g_xlo[e[i]] = make_uint4(lo[0], lo[1], lo[2], lo[3]);
        }
    } else {
        float4 a[4], b[4];
        int e[4];
        #pragma unroll
        for (int i = 0; i < 4; i++) {
            e[i] = (bx - 384) * 256 + t + i * 1536;
            int which = e[i] >> 11;
            int wo = (e[i] & 2047) * 8;
            const float* s = ((which == 0) ? wq : (which == 1) ? wk : wv) + wo;
            a[i] = *(const float4*)s;
            b[i] = *(const float4*)(s + 4);
        }
        #pragma unroll
        for (int i = 0; i < 4; i++) {
            float f[8] = {a[i].x, a[i].y, a[i].z, a[i].w, b[i].x, b[i].y, b[i].z, b[i].w};
            u32 hi[4], lo[4];
            #pragma unroll
            for (int u = 0; u < 4; u++) {
                float h0 = bf_hi(f[2 * u]), h1 = bf_hi(f[2 * u + 1]);
                hi[u] = pk(h0, h1);
                lo[u] = pk(f[2 * u] - h0, f[2 * u + 1] - h1);
            }
            g_whi[e[i]] = make_uint4(hi[0], hi[1], hi[2], hi[3]);
            g_wlo[e[i]] = make_uint4(lo[0], lo[1], lo[2], lo[3]);
        }
    }
}

// ---------------------------------------------------------------- kernel 1
// QKV: 256 threads, 8 warps = 4m(32 rows) x 2n(32 cols). 32x32 warp tiles.
#define QS_XHI 0
#define QS_XLO 16384
#define QS_WHI 32768
#define QS_WLO 40960
#define QS_SIZE 49152
#define QKV_SMEM (2 * QS_SIZE)     // 98304

__global__ __launch_bounds__(256, 2) void qkv_kernel()
{
    extern __shared__ char smc[];
    const u32 sb = smem_u32(smc);
    const int t = threadIdx.x, lane = t & 31, wid = t >> 5;
    const int wm = wid & 3, wn = wid >> 2;       // 4m x 2n
    const int m0 = wm * 32;
    const int r0 = blockIdx.x * 128;
    const int which = blockIdx.y;

    {
        const u32 stg = sb;
        #pragma unroll
        for (int rep = 0; rep < 4; rep++) {
            int idx = t + rep * 256, r = idx >> 3, c = idx & 7;
            u32 off = (u32)(r << 7) + (u32)((c ^ (r & 7)) << 4);
            cp16(stg + QS_XHI + off, &g_xhi[(size_t)(r0 + r) * 32 + c]);
            cp16(stg + QS_XLO + off, &g_xlo[(size_t)(r0 + r) * 32 + c]);
        }
        #pragma unroll
        for (int rep = 0; rep < 2; rep++) {
            int idx = t + rep * 256, r = idx >> 3, c = idx & 7;
            u32 off = (u32)(r << 7) + (u32)((c ^ (r & 7)) << 4);
            cp16(stg + QS_WHI + off, &g_whi[which * 2048 + r * 8 + c]);
            cp16(stg + QS_WLO + off, &g_wlo[which * 2048 + r * 8 + c]);
        }
        CP_COMMIT();
    }

    float acc[2][4][4];
    #pragma unroll
    for (int i = 0; i < 2; i++)
        #pragma unroll
        for (int j = 0; j < 4; j++)
            #pragma unroll
            for (int k = 0; k < 4; k++) acc[i][j][k] = 0.f;

    for (int ch = 0; ch < 4; ch++) {
        CP_WAIT0();
        __syncthreads();
        if (ch < 3) {
            const u32 stg = sb + (u32)((ch + 1) & 1) * QS_SIZE;
            #pragma unroll
            for (int rep = 0; rep < 4; rep++) {
                int idx = t + rep * 256, r = idx >> 3, c = idx & 7;
                u32 off = (u32)(r << 7) + (u32)((c ^ (r & 7)) << 4);
                cp16(stg + QS_XHI + off, &g_xhi[(size_t)(r0 + r) * 32 + (ch + 1) * 8 + c]);
                cp16(stg + QS_XLO + off, &g_xlo[(size_t)(r0 + r) * 32 + (ch + 1) * 8 + c]);
            }
            #pragma unroll
            for (int rep = 0; rep < 2; rep++) {
                int idx = t + rep * 256, r = idx >> 3, c = idx & 7;
                u32 off = (u32)(r << 7) + (u32)((c ^ (r & 7)) << 4);
                cp16(stg + QS_WHI + off, &g_whi[which * 2048 + ((ch + 1) * 64 + r) * 8 + c]);
                cp16(stg + QS_WLO + off, &g_wlo[which * 2048 + ((ch + 1) * 64 + r) * 8 + c]);
            }
            CP_COMMIT();
        }
        const u32 cur = sb + (u32)(ch & 1) * QS_SIZE;
        #pragma unroll
        for (int k16 = 0; k16 < 4; k16++) {
            int k0 = k16 * 16;
            u32 ah[2][4], al[2][4];
            #pragma unroll
            for (int ms = 0; ms < 2; ms++) {
                ldm4(ah[ms], addr_A(cur + QS_XHI, lane, m0 + ms * 16, k0));
                ldm4(al[ms], addr_A(cur + QS_XLO, lane, m0 + ms * 16, k0));
            }
            #pragma unroll
            for (int np = 0; np < 2; np++) {
                u32 bh[4], bl[4];
                ldm4t(bh, addr_A(cur + QS_WHI, lane, k0, wn * 32 + np * 16));
                ldm4t(bl, addr_A(cur + QS_WLO, lane, k0, wn * 32 + np * 16));
                #pragma unroll
                for (int ms = 0; ms < 2; ms++) {
                    mma_bf(acc[ms][np * 2],     ah[ms], bh);
                    mma_bf(acc[ms][np * 2 + 1], ah[ms], bh + 2);
                    mma_bf(acc[ms][np * 2],     ah[ms], bl);
                    mma_bf(acc[ms][np * 2 + 1], ah[ms], bl + 2);
                    mma_bf(acc[ms][np * 2],     al[ms], bh);
                    mma_bf(acc[ms][np * 2 + 1], al[ms], bh + 2);
                }
            }
        }
    }

    const float scale = (which == 0) ? 0.18033688f : 1.0f;
    u32* dh = (u32*)((which == 0) ? g_qhi : (which == 1) ? g_khi : g_vhi);
    u32* dl = (u32*)g_vlo;                       // only V keeps a lo part
    const bool write_lo = (which == 2);
    const int g = lane >> 2, tt = (lane & 3) * 2;
    #pragma unroll
    for (int ms = 0; ms < 2; ms++)
        #pragma unroll
        for (int nf = 0; nf < 4; nf++)
            #pragma unroll
            for (int gg = 0; gg < 2; gg++) {
                int row = r0 + m0 + ms * 16 + g + gg * 8;
                int col = wn * 32 + nf * 8 + tt;
                float v0 = acc[ms][nf][gg * 2] * scale;
                float v1 = acc[ms][nf][gg * 2 + 1] * scale;
                float h0 = bf_hi(v0), h1 = bf_hi(v1);
                dh[row * 32 + (col >> 1)] = pk(h0, h1);
                if (write_lo)
                    dl[row * 32 + (col >> 1)] = pk(v0 - h0, v1 - h1);
            }
}

// ---------------------------------------------------------------- kernel 2
// Flash attention, balanced pairing. Grid 384 = 32 batches x 12 pairs.
// CTA handles 32-row subtiles j and 23-j (13 key-tile units each CTA).
// 128 threads = 2m(16 rows) x 2kg(32 keys). Q_lo and K_lo dropped in S
// (measured err 7.6e-4 < 1e-3); V fully split in PV (3-term, verified).
// Stage = KH+VH+VL = 24KB; smem 52KB; occupancy 3 (reg budget 170, no spill).
#define AQH 0
#define AKV 4096
#define ASTG 24576         // per stage: KH +0, VH +8K, VL +16K
#define A_SMEM (AKV + 2 * ASTG)  // 53248
#define RSTRIDE 72

__global__ __launch_bounds__(128, 3) void attn_kernel(float* __restrict__ out)
{
    extern __shared__ char smc[];
    const u32 sb = smem_u32(smc);
    const int t = threadIdx.x, lane = t & 31, wid = t >> 5;
    const int wm = wid & 1, wg = wid >> 1;       // 2 row-warps x 2 key-groups
    const int m0 = wm * 16;
    const int b  = blockIdx.x & 31;
    const int pr = (int)(blockIdx.x >> 5);       // pair id 0..11
    const size_t tok0 = (size_t)b * SEQ;
    const int g = lane >> 2, tt = (lane & 3) * 2;

    for (int phase = 0; phase < 2; phase++) {
        const int j   = phase ? (23 - pr) : pr;  // subtile 0..23
        const int q0  = j * 32;
        const int nkt = (j >> 1) + 1;            // key tiles (64 keys each)

        __syncthreads();                          // prev phase epilogue done

        // prologue: Q hi (32 rows) + KV tile 0
        #pragma unroll
        for (int rep = 0; rep < 2; rep++) {
            int idx = t + rep * 128, r = idx >> 3, c = idx & 7;
            u32 off = (u32)(r << 7) + (u32)((c ^ (r & 7)) << 4);
            cp16(sb + AQH + off, &g_qhi[(tok0 + q0 + r) * 8 + c]);
        }
        #pragma unroll
        for (int rep = 0; rep < 4; rep++) {
            int idx = t + rep * 128, r = idx >> 3, c = idx & 7;
            u32 off = (u32)(r << 7) + (u32)((c ^ (r & 7)) << 4);
            cp16(sb + AKV + 0     + off, &g_khi[(tok0 + r) * 8 + c]);
            cp16(sb + AKV + 8192  + off, &g_vhi[(tok0 + r) * 8 + c]);
            cp16(sb + AKV + 16384 + off, &g_vlo[(tok0 + r) * 8 + c]);
        }
        CP_COMMIT();

        float oacc[8][4];
        #pragma unroll
        for (int i = 0; i < 8; i++)
            #pragma unroll
            for (int jj = 0; jj < 4; jj++) oacc[i][jj] = 0.f;
        float ls0 = 0.f, ls1 = 0.f;

        for (int kt = 0; kt < nkt; kt++) {
            CP_WAIT0();                           // tile kt resident
            __syncthreads();                      // all warps done with other stage
            if (kt + 1 < nkt) {                   // issue next tile
                const u32 stg = sb + AKV + (u32)((kt + 1) & 1) * ASTG;
                const size_t nb = tok0 + (size_t)(kt + 1) * 64;
                #pragma unroll
                for (int rep = 0; rep < 4; rep++) {
                    int idx = t + rep * 128, r = idx >> 3, c = idx & 7;
                    u32 off = (u32)(r << 7) + (u32)((c ^ (r & 7)) << 4);
                    cp16(stg + 0     + off, &g_khi[(nb + r) * 8 + c]);
                    cp16(stg + 8192  + off, &g_vhi[(nb + r) * 8 + c]);
                    cp16(stg + 16384 + off, &g_vlo[(nb + r) * 8 + c]);
                }
                CP_COMMIT();
            }
            const u32 cur = sb + AKV + (u32)(kt & 1) * ASTG;

            const bool last = (kt == nkt - 1);
            const int kb0 = kt * 64 + wg * 32;
            if (!last || kb0 <= q0 + m0 + 15) {   // warp-granular causal skip
                // ---- S = Qhi Khi^T (16 rows x 32 keys), single term
                float sacc[4][4];
                #pragma unroll
                for (int i = 0; i < 4; i++)
                    #pragma unroll
                    for (int jj = 0; jj < 4; jj++) sacc[i][jj] = 0.f;
                #pragma unroll
                for (int k16 = 0; k16 < 4; k16++) {
                    int k0 = k16 * 16;
                    u32 ah[4];
                    ldm4(ah, addr_A(sb + AQH, lane, m0, k0));
                    #pragma unroll
                    for (int np = 0; np < 2; np++) {
                        int n0 = wg * 32 + np * 16;
                        u32 bh[4];
                        ldm4(bh, addr_B(cur + 0, lane, n0, k0));
                        mma_bf(sacc[np * 2],     ah, bh);
                        mma_bf(sacc[np * 2 + 1], ah, bh + 2);
                    }
                }

                // ---- softmax (fixed bias; scale*log2e folded into Q)
                const int rowg = q0 + m0 + g;
                u32 ph[2][4], pl[2][4];
                #pragma unroll
                for (int f = 0; f < 4; f++) {
                    int cb = kb0 + f * 8 + tt;
                    float p0 = ex2(sacc[f][0]), p1 = ex2(sacc[f][1]);
                    float p2 = ex2(sacc[f][2]), p3 = ex2(sacc[f][3]);
                    if (last) {
                        if (cb     > rowg)     p0 = 0.f;
                        if (cb + 1 > rowg)     p1 = 0.f;
                        if (cb     > rowg + 8) p2 = 0.f;
                        if (cb + 1 > rowg + 8) p3 = 0.f;
                    }
                    ls0 += p0 + p1;
                    ls1 += p2 + p3;
                    float h0 = bf_hi(p0), h1 = bf_hi(p1), h2 = bf_hi(p2), h3 = bf_hi(p3);
                    int jf = f >> 1, hv = (f & 1) * 2;
                    ph[jf][hv]     = pk(h0, h1);
                    ph[jf][hv + 1] = pk(h2, h3);
                    pl[jf][hv]     = pk(p0 - h0, p1 - h1);
                    pl[jf][hv + 1] = pk(p2 - h2, p3 - h3);
                }

                // ---- O += P V over this group's 32 keys (3-term split)
                #pragma unroll
                for (int np = 0; np < 4; np++) {
                    int n0 = np * 16;
                    #pragma unroll
                    for (int jj = 0; jj < 2; jj++) {
                        int k0v = wg * 32 + jj * 16;
                        u32 bh[4], bl[4];
                        ldm4t(bh, addr_A(cur + 8192,  lane, k0v, n0));
                        ldm4t(bl, addr_A(cur + 16384, lane, k0v, n0));
                        mma_bf(oacc[np * 2],     ph[jj], bh);
                        mma_bf(oacc[np * 2 + 1], ph[jj], bh + 2);
                        mma_bf(oacc[np * 2],     ph[jj], bl);
                        mma_bf(oacc[np * 2 + 1], ph[jj], bl + 2);
                        mma_bf(oacc[np * 2],     pl[jj], bh);
                        mma_bf(oacc[np * 2 + 1], pl[jj], bh + 2);
                    }
                }
            }
        }

        // ---- cross-group reduction: wg1 -> smem, wg0 adds + writes
        ls0 += __shfl_xor_sync(0xffffffffu, ls0, 1);
        ls0 += __shfl_xor_sync(0xffffffffu, ls0, 2);
        ls1 += __shfl_xor_sync(0xffffffffu, ls1, 1);
        ls1 += __shfl_xor_sync(0xffffffffu, ls1, 2);

        __syncthreads();                          // all PV reads of KV smem done
        float* red  = (float*)(smc + AKV);                    // 32 x RSTRIDE
        float* lred = (float*)(smc + AKV + 32 * RSTRIDE * 4); // 32 floats

        if (wg == 1) {
            int row0 = m0 + g;
            #pragma unroll
            for (int np = 0; np < 4; np++)
                #pragma unroll
                for (int h = 0; h < 2; h++) {
                    int col = np * 16 + h * 8 + tt;
                    *(float2*)&red[row0 * RSTRIDE + col] =
                        make_float2(oacc[np * 2 + h][0], oacc[np * 2 + h][1]);
                    *(float2*)&red[(row0 + 8) * RSTRIDE + col] =
                        make_float2(oacc[np * 2 + h][2], oacc[np * 2 + h][3]);
                }
            if ((lane & 3) == 0) {
                lred[row0]     = ls0;
                lred[row0 + 8] = ls1;
            }
        }
        __syncthreads();
        if (wg == 0) {
            int row0 = m0 + g;
            float inv0 = 1.0f / (ls0 + lred[row0]);
            float inv1 = 1.0f / (ls1 + lred[row0 + 8]);
            float* op0 = out + (tok0 + q0 + row0) * HDIM;
            float* op1 = out + (tok0 + q0 + row0 + 8) * HDIM;
            #pragma unroll
            for (int np = 0; np < 4; np++)
                #pragma unroll
                for (int h = 0; h < 2; h++) {
                    int col = np * 16 + h * 8 + tt;
                    float2 a0 = *(float2*)&red[row0 * RSTRIDE + col];
                    float2 a1 = *(float2*)&red[(row0 + 8) * RSTRIDE + col];
                    *(float2*)(op0 + col) = make_float2(
                        (oacc[np * 2 + h][0] + a0.x) * inv0,
                        (oacc[np * 2 + h][1] + a0.y) * inv0);
                    *(float2*)(op1 + col) = make_float2(
                        (oacc[np * 2 + h][2] + a1.x) * inv1,
                        (oacc[np * 2 + h][3] + a1.y) * inv1);
                }
        }
    }
}

// ---------------------------------------------------------------- launch
extern "C" void kernel_launch(void* const* d_in, const int* in_sizes, int n_in,
                              void* d_out, int out_size)
{
    const float* x  = (const float*)d_in[0];
    const float* wq = (const float*)d_in[1];
    const float* wk = (const float*)d_in[2];
    const float* wv = (const float*)d_in[3];
    float* out = (float*)d_out;

    cudaFuncSetAttribute(qkv_kernel,  cudaFuncAttributeMaxDynamicSharedMemorySize, QKV_SMEM);
    cudaFuncSetAttribute(attn_kernel, cudaFuncAttributeMaxDynamicSharedMemorySize, A_SMEM);

    split_kernel<<<390, 256>>>(x, wq, wk, wv);
    qkv_kernel<<<dim3(192, 3), 256, QKV_SMEM>>>();
    attn_kernel<<<384, 128, A_SMEM>>>(out);
}